// round 4
// baseline (speedup 1.0000x reference)
#include <cuda_runtime.h>
#include <cstdint>
#include <cfloat>

#define NGRAPH 100
#define NNODE  2500
#define NEDGE  7500
#define TT     52
#define NTOK   104   // 52 * B(2)

typedef unsigned long long ull;

// ---------------- scratch (static device arrays; no cudaMalloc anywhere) ----------------
__device__ float d_x0[NGRAPH * NNODE * 64];    //  64 MB  embed output
__device__ float d_u1[NGRAPH * NNODE * 64];    //  64 MB  aggregated x0
__device__ float d_h1[NGRAPH * NNODE * 128];   // 128 MB  layer-1 output
__device__ float d_u2[NGRAPH * NNODE * 128];   // 128 MB  aggregated h1
__device__ int      d_cnt   [NGRAPH * NNODE];
__device__ int      d_start [NGRAPH * NNODE];
__device__ int      d_cursor[NGRAPH * NNODE];
__device__ float    d_dinv  [NGRAPH * NNODE];
__device__ int      d_csr_row[NGRAPH * NEDGE];
__device__ float    d_csr_w  [NGRAPH * NEDGE];
__device__ unsigned d_pool[NGRAPH * 256];
__device__ float d_xseq  [NTOK * 32];
__device__ float d_qkv   [NTOK * 96];
__device__ float d_attn  [NTOK * 32];

// ---------------- helpers ----------------
__device__ __forceinline__ float lrelu(float x) { return x >= 0.f ? x : 0.15f * x; }

// order-preserving float -> uint mapping for atomicMax-based max-pool
__device__ __forceinline__ unsigned fmap(float f) {
    unsigned u = __float_as_uint(f);
    return (f >= 0.f) ? (u | 0x80000000u) : ~u;
}
__device__ __forceinline__ float funmap(unsigned u) {
    return (u & 0x80000000u) ? __uint_as_float(u & 0x7FFFFFFFu) : __uint_as_float(~u);
}
__device__ __forceinline__ float wsum(float v) {
#pragma unroll
    for (int o = 16; o > 0; o >>= 1) v += __shfl_xor_sync(0xffffffffu, v, o);
    return v;
}

// ---- Blackwell packed dual-FP32 (PTX-only; ptxas never auto-fuses) ----
__device__ __forceinline__ ull pack2(float lo, float hi) {
    ull r;
    asm("mov.b64 %0, {%1, %2};" : "=l"(r) : "f"(lo), "f"(hi));
    return r;
}
__device__ __forceinline__ ull fma2(ull a, ull b, ull c) {
    ull d;
    asm("fma.rn.f32x2 %0, %1, %2, %3;" : "=l"(d) : "l"(a), "l"(b), "l"(c));
    return d;
}
__device__ __forceinline__ float2 unpack2(ull v) {
    float2 f;
    asm("mov.b64 {%0, %1}, %2;" : "=f"(f.x), "=f"(f.y) : "l"(v));
    return f;
}

// ---------------- init ----------------
__global__ void zero_kernel() {
    int i = blockIdx.x * 256 + threadIdx.x;
    if (i < NGRAPH * NNODE) d_cnt[i] = 0;
    if (i < NGRAPH * 256)   d_pool[i] = 0u;   // 0 < fmap(any finite float): acts as -inf
}

// ---------------- embed: x0 = relu(v @ W_emb + b_emb) ----------------
__global__ void embed_kernel(const float* __restrict__ v, const float* __restrict__ W,
                             const float* __restrict__ b) {
    int i = blockIdx.x * 256 + threadIdx.x;
    if (i >= NGRAPH * NNODE * 64) return;
    int row = i >> 6, d = i & 63;
    const float* vr = v + row * 3;
    float s = b[d] + vr[0] * W[d] + vr[1] * W[64 + d] + vr[2] * W[128 + d];
    d_x0[i] = fmaxf(s, 0.f);
}

// ---------------- CSR build (counting sort by destination) ----------------
__global__ void count_kernel(const int* __restrict__ el) {
    int i = blockIdx.x * 256 + threadIdx.x;
    if (i >= NGRAPH * NEDGE) return;
    int g = i / NEDGE;
    int col = el[2 * i + 1];
    atomicAdd(&d_cnt[g * NNODE + col], 1);
}

__global__ void scan_kernel() {   // one block per graph: exclusive prefix of cnt; also dinv
    const int g = blockIdx.x;
    __shared__ int sm[256];
    __shared__ int carry;
    const int tid = threadIdx.x;
    if (tid == 0) carry = 0;
    __syncthreads();
    for (int base = 0; base < NNODE; base += 256) {
        const int i = base + tid;
        int v = (i < NNODE) ? d_cnt[g * NNODE + i] : 0;
        sm[tid] = v;
        __syncthreads();
        for (int off = 1; off < 256; off <<= 1) {
            int t = (tid >= off) ? sm[tid - off] : 0;
            __syncthreads();
            sm[tid] += t;
            __syncthreads();
        }
        const int incl = sm[tid];
        const int total = sm[255];
        if (i < NNODE) {
            const int st = carry + incl - v;
            d_start [g * NNODE + i] = st;
            d_cursor[g * NNODE + i] = st;
            d_dinv  [g * NNODE + i] = rsqrtf((float)v + 1.0f);
        }
        __syncthreads();
        if (tid == 0) carry += total;
        __syncthreads();
    }
}

__global__ void fill_kernel(const int* __restrict__ el) {
    int i = blockIdx.x * 256 + threadIdx.x;
    if (i >= NGRAPH * NEDGE) return;
    int g = i / NEDGE;
    int row = el[2 * i], col = el[2 * i + 1];
    int p = atomicAdd(&d_cursor[g * NNODE + col], 1);
    d_csr_row[g * NEDGE + p] = row;
    d_csr_w  [g * NEDGE + p] = d_dinv[g * NNODE + row] * d_dinv[g * NNODE + col];
}

// ---------------- gather BEFORE gemm (exact: agg(x)@W == agg(x@W)) ----------------
// u = sum_e nrm*x[row_e] + dinv^2 * x    (no bias / activation here)
// warp-per-node; edge loop unrolled x2 for MLP.
__global__ void gather64_kernel() {     // x0 (64-wide) -> u1
    const int g = blockIdx.y;
    const int warp = threadIdx.x >> 5, lane = threadIdx.x & 31;
    const int node = blockIdx.x * 8 + warp;
    if (node >= NNODE) return;
    const int base = g * NNODE + node;
    const int s0 = d_start[base], c = d_cnt[base];
    const float* xg = d_x0 + (size_t)g * NNODE * 64;
    float2 acc = make_float2(0.f, 0.f);
    int e = 0;
    for (; e + 2 <= c; e += 2) {
        const int idx = g * NEDGE + s0 + e;
        const int r0 = d_csr_row[idx],     r1 = d_csr_row[idx + 1];
        const float w0 = d_csr_w[idx],     w1 = d_csr_w[idx + 1];
        float2 a = *reinterpret_cast<const float2*>(xg + (size_t)r0 * 64 + lane * 2);
        float2 b = *reinterpret_cast<const float2*>(xg + (size_t)r1 * 64 + lane * 2);
        acc.x += w0 * a.x + w1 * b.x;
        acc.y += w0 * a.y + w1 * b.y;
    }
    if (e < c) {
        const int idx = g * NEDGE + s0 + e;
        const int r = d_csr_row[idx];
        const float w = d_csr_w[idx];
        float2 a = *reinterpret_cast<const float2*>(xg + (size_t)r * 64 + lane * 2);
        acc.x += w * a.x; acc.y += w * a.y;
    }
    const float di = d_dinv[base];
    const float ws = di * di;
    float2 xv = *reinterpret_cast<const float2*>(xg + (size_t)node * 64 + lane * 2);
    acc.x += ws * xv.x; acc.y += ws * xv.y;
    *reinterpret_cast<float2*>(d_u1 + (size_t)base * 64 + lane * 2) = acc;
}

__global__ void gather128_kernel() {    // h1 (128-wide) -> u2
    const int g = blockIdx.y;
    const int warp = threadIdx.x >> 5, lane = threadIdx.x & 31;
    const int node = blockIdx.x * 8 + warp;
    if (node >= NNODE) return;
    const int base = g * NNODE + node;
    const int s0 = d_start[base], c = d_cnt[base];
    const float* xg = d_h1 + (size_t)g * NNODE * 128;
    float4 acc = make_float4(0.f, 0.f, 0.f, 0.f);
    int e = 0;
    for (; e + 2 <= c; e += 2) {
        const int idx = g * NEDGE + s0 + e;
        const int r0 = d_csr_row[idx],     r1 = d_csr_row[idx + 1];
        const float w0 = d_csr_w[idx],     w1 = d_csr_w[idx + 1];
        float4 a = *reinterpret_cast<const float4*>(xg + (size_t)r0 * 128 + lane * 4);
        float4 b = *reinterpret_cast<const float4*>(xg + (size_t)r1 * 128 + lane * 4);
        acc.x += w0 * a.x + w1 * b.x;
        acc.y += w0 * a.y + w1 * b.y;
        acc.z += w0 * a.z + w1 * b.z;
        acc.w += w0 * a.w + w1 * b.w;
    }
    if (e < c) {
        const int idx = g * NEDGE + s0 + e;
        const int r = d_csr_row[idx];
        const float w = d_csr_w[idx];
        float4 a = *reinterpret_cast<const float4*>(xg + (size_t)r * 128 + lane * 4);
        acc.x += w * a.x; acc.y += w * a.y; acc.z += w * a.z; acc.w += w * a.w;
    }
    const float di = d_dinv[base];
    const float ws = di * di;
    float4 xv = *reinterpret_cast<const float4*>(xg + (size_t)node * 128 + lane * 4);
    acc.x += ws * xv.x; acc.y += ws * xv.y; acc.z += ws * xv.z; acc.w += ws * xv.w;
    *reinterpret_cast<float4*>(d_u2 + (size_t)base * 128 + lane * 4) = acc;
}

// ---------------- SGEMM (f32x2 packed), 128x128 tile, 8x8 microtile ----------------
// WHICH==1: h1 = lrelu(u1 @ W1 + b1)         (K=64,  NOUT=128, writes h1)
// WHICH==2: pool = max_n lrelu(u2 @ W2 + b2) (K=128, NOUT=256, fused maxpool, no C)
template <int K, int NOUT, int WHICH>
__launch_bounds__(256, 2)
__global__ void gemm_kernel(const float* __restrict__ W, const float* __restrict__ bias) {
    const float* A = (WHICH == 1) ? d_u1 : d_u2;
    const int g = blockIdx.z;
    __shared__ float As[16][128];   // [k][m]
    __shared__ float Bs[16][128];   // [k][n]
    const float* Ag = A + (size_t)g * NNODE * K;
    const int row0 = blockIdx.x * 128;
    const int col0 = blockIdx.y * 128;
    const int tid = threadIdx.x;
    const int tm = (tid >> 4) << 3;
    const int tn = (tid & 15) << 3;
    ull acc2[8][4];
#pragma unroll
    for (int i = 0; i < 8; i++)
#pragma unroll
        for (int j = 0; j < 4; j++) acc2[i][j] = 0ull;

    for (int kt = 0; kt < K; kt += 16) {
        // A tile: 128 rows x 16 k (transposed store)
#pragma unroll
        for (int i = 0; i < 2; i++) {
            int lin = tid + i * 256;          // float4 index 0..511
            int r   = lin >> 2;               // 0..127
            int kk  = (lin & 3) * 4;
            float4 v4 = make_float4(0.f, 0.f, 0.f, 0.f);
            int grow = row0 + r;
            if (grow < NNODE)
                v4 = *reinterpret_cast<const float4*>(Ag + (size_t)grow * K + kt + kk);
            As[kk + 0][r] = v4.x; As[kk + 1][r] = v4.y;
            As[kk + 2][r] = v4.z; As[kk + 3][r] = v4.w;
        }
        // B tile: 16 k x 128 n
#pragma unroll
        for (int i = 0; i < 2; i++) {
            int lin = tid + i * 256;
            int kk  = lin >> 5;               // 0..15
            int n4  = (lin & 31) * 4;
            float4 v4 = *reinterpret_cast<const float4*>(W + (size_t)(kt + kk) * NOUT + col0 + n4);
            *reinterpret_cast<float4*>(&Bs[kk][n4]) = v4;
        }
        __syncthreads();
#pragma unroll
        for (int k = 0; k < 16; k++) {
            float2 a2[4];
            ull    b2[4];
#pragma unroll
            for (int p = 0; p < 4; p++)
                a2[p] = *reinterpret_cast<const float2*>(&As[k][tm + 2 * p]);
#pragma unroll
            for (int p = 0; p < 4; p++)
                b2[p] = *reinterpret_cast<const ull*>(&Bs[k][tn + 2 * p]);
#pragma unroll
            for (int i = 0; i < 8; i++) {
                float av = (i & 1) ? a2[i >> 1].y : a2[i >> 1].x;
                ull ap = pack2(av, av);
#pragma unroll
                for (int j = 0; j < 4; j++) acc2[i][j] = fma2(ap, b2[j], acc2[i][j]);
            }
        }
        __syncthreads();
    }

    float bcol[8];
#pragma unroll
    for (int j = 0; j < 8; j++) bcol[j] = bias[col0 + tn + j];

    if (WHICH == 1) {
#pragma unroll
        for (int i = 0; i < 8; i++) {
            int r = row0 + tm + i;
            if (r < NNODE) {
                float o[8];
#pragma unroll
                for (int p = 0; p < 4; p++) {
                    float2 u = unpack2(acc2[i][p]);
                    o[2 * p]     = lrelu(u.x + bcol[2 * p]);
                    o[2 * p + 1] = lrelu(u.y + bcol[2 * p + 1]);
                }
                float* dst = d_h1 + ((size_t)g * NNODE + r) * 128 + tn;
                *reinterpret_cast<float4*>(dst)     = make_float4(o[0], o[1], o[2], o[3]);
                *reinterpret_cast<float4*>(dst + 4) = make_float4(o[4], o[5], o[6], o[7]);
            }
        }
    } else {
        // fused leaky + node-maxpool; nothing written to HBM except pool atomics
        float cmax[8];
#pragma unroll
        for (int j = 0; j < 8; j++) cmax[j] = -FLT_MAX;
#pragma unroll
        for (int i = 0; i < 8; i++) {
            int r = row0 + tm + i;
            if (r < NNODE) {
#pragma unroll
                for (int p = 0; p < 4; p++) {
                    float2 u = unpack2(acc2[i][p]);
                    cmax[2 * p]     = fmaxf(cmax[2 * p],     lrelu(u.x + bcol[2 * p]));
                    cmax[2 * p + 1] = fmaxf(cmax[2 * p + 1], lrelu(u.y + bcol[2 * p + 1]));
                }
            }
        }
        __syncthreads();                 // reuse As as reduction scratch [16][128]
        float* red = &As[0][0];
#pragma unroll
        for (int j = 0; j < 8; j++) red[(tm >> 3) * 128 + tn + j] = cmax[j];
        __syncthreads();
        if (tid < 128) {
            float m = red[tid];
#pragma unroll
            for (int r = 1; r < 16; r++) m = fmaxf(m, red[r * 128 + tid]);
            atomicMax(&d_pool[g * 256 + col0 + tid], fmap(m));
        }
    }
}

// ---------------- fc + seq build: xseq = [mu; sigma; relu(pool@Wfc+bfc)] + pe ----------------
__global__ void fc_kernel(const float* __restrict__ Wfc, const float* __restrict__ bfc,
                          const float* __restrict__ muQ, const float* __restrict__ sigmaQ,
                          const float* __restrict__ pe) {
    const int g = blockIdx.x;
    const int d = threadIdx.x;   // 32
    if (g >= NGRAPH) {
        int t = g - NGRAPH;      // token 0 or 1
        const float* src = (t == 0) ? muQ : sigmaQ;
        float v = src[d] + pe[t * 32 + d];
        d_xseq[t * 64 + d]      = v;   // b = 0
        d_xseq[t * 64 + 32 + d] = v;   // b = 1
        return;
    }
    __shared__ float sp[256];
    for (int j = d; j < 256; j += 32) sp[j] = funmap(d_pool[g * 256 + j]);
    __syncwarp();
    float s = bfc[d];
#pragma unroll 8
    for (int j = 0; j < 256; j++) s += sp[j] * Wfc[j * 32 + d];
    const int b = g / 50, t = (g % 50) + 2;
    d_xseq[t * 64 + b * 32 + d] = fmaxf(s, 0.f) + pe[t * 32 + d];
}

// ---------------- transformer: qkv (per token) ----------------
__global__ void qkv_kernel(const float* __restrict__ iw, const float* __restrict__ ib) {
    __shared__ float sx[32];
    const int tok = blockIdx.x;
    if (threadIdx.x < 32) sx[threadIdx.x] = d_xseq[tok * 32 + threadIdx.x];
    __syncthreads();
    const int j = threadIdx.x;   // 96
    float s = ib[j];
    const float* wr = iw + j * 32;
#pragma unroll
    for (int k = 0; k < 32; k++) s += sx[k] * wr[k];
    d_qkv[tok * 96 + j] = s;
}

// ---------------- transformer: attention (per batch,head) ----------------
__global__ void attn_kernel() {
    __shared__ float sQ[TT][8], sK[TT][8], sV[TT][8];
    const int b = blockIdx.x >> 2, h = blockIdx.x & 3;
    for (int idx = threadIdx.x; idx < TT * 8; idx += 64) {
        int t = idx >> 3, d = idx & 7;
        int base = (t * 2 + b) * 96 + h * 8 + d;
        sQ[t][d] = d_qkv[base];
        sK[t][d] = d_qkv[base + 32];
        sV[t][d] = d_qkv[base + 64];
    }
    __syncthreads();
    const int t = threadIdx.x;
    if (t < TT) {
        const float scale = 0.35355339059327373f;
        float m = -3.4e38f;
        for (int s = 0; s < TT; s++) {
            float d0 = 0.f;
#pragma unroll
            for (int d = 0; d < 8; d++) d0 += sQ[t][d] * sK[s][d];
            m = fmaxf(m, d0 * scale);
        }
        float sum = 0.f, o[8] = {0, 0, 0, 0, 0, 0, 0, 0};
        for (int s = 0; s < TT; s++) {
            float d0 = 0.f;
#pragma unroll
            for (int d = 0; d < 8; d++) d0 += sQ[t][d] * sK[s][d];
            float p = expf(d0 * scale - m);
            sum += p;
#pragma unroll
            for (int d = 0; d < 8; d++) o[d] += p * sV[s][d];
        }
        float inv = 1.0f / sum;
        int ob = (t * 2 + b) * 32 + h * 8;
#pragma unroll
        for (int d = 0; d < 8; d++) d_attn[ob + d] = o[d] * inv;
    }
}

// ---------------- transformer: fused proj + ln1 + ff1 + gelu + ff2 + ln2 (per token) ----------------
__global__ __launch_bounds__(256)
void mix_kernel(const float* __restrict__ ow, const float* __restrict__ ob,
                const float* __restrict__ lg1, const float* __restrict__ lb1,
                const float* __restrict__ w1, const float* __restrict__ b1,
                const float* __restrict__ w2, const float* __restrict__ b2,
                const float* __restrict__ lg2, const float* __restrict__ lb2) {
    const int tok = blockIdx.x;
    const int tid = threadIdx.x;
    __shared__ float so[32];     // attention output for this token
    __shared__ float sx[32];     // after ln1 (residual base for ff)
    __shared__ float hid[1024];  // ff hidden (never leaves SMEM)
    __shared__ float part[256];

    if (tid < 32) so[tid] = d_attn[tok * 32 + tid];
    __syncthreads();

    // proj + residual + ln1 (warp 0)
    if (tid < 32) {
        const int d = tid;
        float s = ob[d];
        const float* wr = ow + d * 32;
#pragma unroll
        for (int j = 0; j < 32; j++) s += so[j] * wr[j];
        float v = d_xseq[tok * 32 + d] + s;
        float m = wsum(v) * (1.f / 32.f);
        float df = v - m;
        float var = wsum(df * df) * (1.f / 32.f);
        sx[d] = df * rsqrtf(var + 1e-5f) * lg1[d] + lb1[d];
    }
    __syncthreads();

    // ff1 + exact gelu: each thread computes 4 hidden units
#pragma unroll
    for (int r = 0; r < 4; r++) {
        int j = tid + r * 256;
        float s = b1[j];
        const float* wr = w1 + j * 32;
#pragma unroll
        for (int k = 0; k < 32; k++) s += sx[k] * wr[k];
        hid[j] = 0.5f * s * (1.0f + erff(s * 0.7071067811865475f));
    }
    __syncthreads();

    // ff2: thread (d, q) sums 128 elems of the 1024-dot for output d
    {
        const int d = tid & 31;
        const int q = tid >> 5;          // 0..7
        const float* hp = hid + q * 128;
        const float* wr = w2 + d * 1024 + q * 128;
        float s = 0.f;
#pragma unroll 8
        for (int j = 0; j < 128; j++) s += hp[j] * wr[j];
        part[tid] = s;
    }
    __syncthreads();

    // reduce 8 partials, residual (with sx), ln2, write back
    if (tid < 32) {
        const int d = tid;
        float t = b2[d];
#pragma unroll
        for (int q = 0; q < 8; q++) t += part[q * 32 + d];
        float v = sx[d] + t;
        float m = wsum(v) * (1.f / 32.f);
        float df = v - m;
        float var = wsum(df * df) * (1.f / 32.f);
        d_xseq[tok * 32 + d] = df * rsqrtf(var + 1e-5f) * lg2[d] + lb2[d];
    }
}

// ---------------- output: concat(mu, logvar, xseq) ----------------
__global__ void out_kernel(float* __restrict__ out, int n) {
    int i = blockIdx.x * 256 + threadIdx.x;
    if (i >= n) return;
    out[i] = (i < 128) ? d_xseq[i] : d_xseq[i - 128];
}

// ---------------- launch ----------------
extern "C" void kernel_launch(void* const* d_in, const int* in_sizes, int n_in,
                              void* d_out, int out_size) {
    const float* v      = (const float*)d_in[0];
    const int*   el     = (const int*)  d_in[2];
    const float* W_emb  = (const float*)d_in[3];
    const float* b_emb  = (const float*)d_in[4];
    const float* W_g1   = (const float*)d_in[5];
    const float* b_g1   = (const float*)d_in[6];
    const float* W_g2   = (const float*)d_in[7];
    const float* b_g2   = (const float*)d_in[8];
    const float* W_fc   = (const float*)d_in[9];
    const float* b_fc   = (const float*)d_in[10];
    const float* muQ    = (const float*)d_in[11];
    const float* sigmaQ = (const float*)d_in[12];
    const float* pe     = (const float*)d_in[13];
    const float* in_w   = (const float*)d_in[14];
    const float* in_b   = (const float*)d_in[15];
    const float* out_w  = (const float*)d_in[16];
    const float* out_b  = (const float*)d_in[17];
    const float* ln1g   = (const float*)d_in[18];
    const float* ln1b   = (const float*)d_in[19];
    const float* w1     = (const float*)d_in[20];
    const float* b1     = (const float*)d_in[21];
    const float* w2     = (const float*)d_in[22];
    const float* b2     = (const float*)d_in[23];
    const float* ln2g   = (const float*)d_in[24];
    const float* ln2b   = (const float*)d_in[25];

    zero_kernel <<<(NGRAPH * NNODE + 255) / 256, 256>>>();
    embed_kernel<<<(NGRAPH * NNODE * 64 + 255) / 256, 256>>>(v, W_emb, b_emb);
    count_kernel<<<(NGRAPH * NEDGE + 255) / 256, 256>>>(el);
    scan_kernel <<<NGRAPH, 256>>>();
    fill_kernel <<<(NGRAPH * NEDGE + 255) / 256, 256>>>(el);

    gather64_kernel <<<dim3((NNODE + 7) / 8, NGRAPH), 256>>>();
    gemm_kernel<64, 128, 1>  <<<dim3(20, 1, NGRAPH), 256>>>(W_g1, b_g1);
    gather128_kernel<<<dim3((NNODE + 7) / 8, NGRAPH), 256>>>();
    gemm_kernel<128, 256, 2> <<<dim3(20, 2, NGRAPH), 256>>>(W_g2, b_g2);

    fc_kernel <<<NGRAPH + 2, 32>>>(W_fc, b_fc, muQ, sigmaQ, pe);

    for (int l = 0; l < 4; l++) {
        qkv_kernel <<<NTOK, 96>>>(in_w + l * 96 * 32, in_b + l * 96);
        attn_kernel<<<8, 64>>>();
        mix_kernel <<<NTOK, 256>>>(out_w + l * 32 * 32, out_b + l * 32,
                                   ln1g + l * 32, ln1b + l * 32,
                                   w1 + l * 1024 * 32, b1 + l * 1024,
                                   w2 + l * 32 * 1024, b2 + l * 32,
                                   ln2g + l * 32, ln2b + l * 32);
    }

    out_kernel<<<(out_size + 255) / 256, 256>>>((float*)d_out, out_size);
}